// round 1
// baseline (speedup 1.0000x reference)
#include <cuda_runtime.h>
#include <math.h>

#define SEQ     2048
#define BATCH   2
#define DMODEL  768
#define NH      12
#define HD      64
#define NTOK    (SEQ*BATCH)   // 4096
#define KB      32            // key tile

// Scratch (allocation-free rule: __device__ globals)
__device__ float g_q[NTOK*DMODEL];
__device__ float g_k[NTOK*DMODEL];
__device__ float g_v[NTOK*DMODEL];
__device__ float g_y[NTOK*DMODEL];

// ---------------------------------------------------------------------------
// Tiled fp32 GEMM: C[M,N] = A[M,K] @ B[K,N] + bias[N]
// BM=BN=64, BK=16, 256 threads, 4x4 micro-tile.
// M=4096, N=768, K=768 -> exact tiling, no bounds checks.
// ---------------------------------------------------------------------------
__global__ __launch_bounds__(256) void gemm_bias_kernel(
    const float* __restrict__ A, const float* __restrict__ B,
    const float* __restrict__ bias, float* __restrict__ C,
    int M, int N, int K)
{
    __shared__ float As[64][20];   // row-major [m][k], pad 20 (80B, 16B-aligned rows)
    __shared__ float Bs[16][64];   // [k][n]

    const int tid = threadIdx.x;
    const int ty  = tid >> 4;      // 0..15
    const int tx  = tid & 15;      // 0..15
    const int m0  = blockIdx.y * 64;
    const int n0  = blockIdx.x * 64;

    const int am  = tid >> 2;      // A load: row 0..63
    const int ac4 = tid & 3;       // A load: float4 col 0..3
    const int bk  = tid >> 4;      // B load: k row 0..15
    const int bc4 = tid & 15;      // B load: float4 col 0..15

    float c[4][4] = {};

    for (int k0 = 0; k0 < K; k0 += 16) {
        // prefetch to registers before the barrier
        float4 a4 = *(const float4*)&A[(size_t)(m0+am)*K + k0 + ac4*4];
        float4 b4 = *(const float4*)&B[(size_t)(k0+bk)*N + n0 + bc4*4];
        __syncthreads();
        *(float4*)&As[am][ac4*4] = a4;
        *(float4*)&Bs[bk][bc4*4] = b4;
        __syncthreads();

        #pragma unroll
        for (int kk = 0; kk < 16; kk++) {
            float a0 = As[ty*4+0][kk];
            float a1 = As[ty*4+1][kk];
            float a2 = As[ty*4+2][kk];
            float a3 = As[ty*4+3][kk];
            float4 b = *(const float4*)&Bs[kk][tx*4];
            c[0][0] += a0*b.x; c[0][1] += a0*b.y; c[0][2] += a0*b.z; c[0][3] += a0*b.w;
            c[1][0] += a1*b.x; c[1][1] += a1*b.y; c[1][2] += a1*b.z; c[1][3] += a1*b.w;
            c[2][0] += a2*b.x; c[2][1] += a2*b.y; c[2][2] += a2*b.z; c[2][3] += a2*b.w;
            c[3][0] += a3*b.x; c[3][1] += a3*b.y; c[3][2] += a3*b.z; c[3][3] += a3*b.w;
        }
    }

    float4 bia = *(const float4*)&bias[n0 + tx*4];
    #pragma unroll
    for (int i = 0; i < 4; i++) {
        float4 r = make_float4(c[i][0]+bia.x, c[i][1]+bia.y, c[i][2]+bia.z, c[i][3]+bia.w);
        *(float4*)&C[(size_t)(m0 + ty*4 + i)*N + n0 + tx*4] = r;
    }
}

// ---------------------------------------------------------------------------
// Causal flash attention: per (batch, head), 64-query x 32-key tiles.
// q/k/v layout: [(s*BATCH+b)*DMODEL + h*HD + d]
// ---------------------------------------------------------------------------
__global__ __launch_bounds__(256) void attn_kernel(
    const float* __restrict__ q, const float* __restrict__ k,
    const float* __restrict__ v, float* __restrict__ y)
{
    __shared__ float Qs[64][64];       // [q_row][d]
    __shared__ float Kst[64][34];      // [d][key]   (d-major -> conflict-free float2 reads)
    __shared__ float Vs[KB][64];       // [key][d_v]
    __shared__ float Ss[64][33];       // scores / probs, pad 33 (odd) for row reductions
    __shared__ float m_s[64], l_s[64], alpha_s[64];

    const int tid = threadIdx.x;
    const int bx  = blockIdx.x;        // q block (0..31)
    const int bh  = blockIdx.y;        // 0..23
    const int b   = bh / NH;
    const int h   = bh % NH;
    const int q0  = bx * 64;
    const int ty  = tid >> 4, tx = tid & 15;

    // Load Q tile: 64 rows x 16 float4
    #pragma unroll
    for (int r = 0; r < 4; r++) {
        int fi  = tid + 256*r;
        int row = fi >> 4, c4 = fi & 15;
        *(float4*)&Qs[row][c4*4] =
            *(const float4*)&q[((size_t)(q0+row)*BATCH + b)*DMODEL + h*HD + c4*4];
    }
    if (tid < 64) { m_s[tid] = -1e30f; l_s[tid] = 0.f; }

    float o[4][4] = {};

    const int nkb = 2*bx + 2;          // key tiles up to (and incl.) diagonal
    for (int kb = 0; kb < nkb; kb++) {
        const int k0 = kb * KB;
        __syncthreads();               // protect Kst/Vs/Ss reuse
        // Load K (transposed to d-major) and V: 32 tokens x 16 float4
        #pragma unroll
        for (int r = 0; r < 2; r++) {
            int fi  = tid + 256*r;
            int tok = fi >> 4, c4 = fi & 15;
            size_t gbase = ((size_t)(k0+tok)*BATCH + b)*DMODEL + h*HD + c4*4;
            float4 kv = *(const float4*)&k[gbase];
            Kst[c4*4+0][tok] = kv.x;
            Kst[c4*4+1][tok] = kv.y;
            Kst[c4*4+2][tok] = kv.z;
            Kst[c4*4+3][tok] = kv.w;
            *(float4*)&Vs[tok][c4*4] = *(const float4*)&v[gbase];
        }
        __syncthreads();

        // Scores: rows ty*4+i (4), cols tx*2+j (2); dot over d=64
        float sc[4][2] = {};
        #pragma unroll
        for (int d = 0; d < 64; d += 4) {
            float2 k0v = *(const float2*)&Kst[d+0][tx*2];
            float2 k1v = *(const float2*)&Kst[d+1][tx*2];
            float2 k2v = *(const float2*)&Kst[d+2][tx*2];
            float2 k3v = *(const float2*)&Kst[d+3][tx*2];
            #pragma unroll
            for (int i = 0; i < 4; i++) {
                float4 q4 = *(const float4*)&Qs[ty*4+i][d];
                sc[i][0] += q4.x*k0v.x + q4.y*k1v.x + q4.z*k2v.x + q4.w*k3v.x;
                sc[i][1] += q4.x*k0v.y + q4.y*k1v.y + q4.z*k2v.y + q4.w*k3v.y;
            }
        }
        // Mask (causal: key <= query), scale, stash
        #pragma unroll
        for (int i = 0; i < 4; i++) {
            int qs = q0 + ty*4 + i;
            #pragma unroll
            for (int j = 0; j < 2; j++) {
                int ks = k0 + tx*2 + j;
                Ss[ty*4+i][tx*2+j] = (ks <= qs) ? sc[i][j]*0.125f : -1e30f;
            }
        }
        __syncthreads();

        // Online softmax update, one thread per row
        if (tid < 64) {
            float mo = m_s[tid];
            float rm = mo;
            #pragma unroll
            for (int c = 0; c < KB; c++) rm = fmaxf(rm, Ss[tid][c]);
            float al  = __expf(mo - rm);
            float sum = 0.f;
            #pragma unroll
            for (int c = 0; c < KB; c++) {
                float p = __expf(Ss[tid][c] - rm);
                Ss[tid][c] = p;
                sum += p;
            }
            m_s[tid]     = rm;
            l_s[tid]     = l_s[tid]*al + sum;
            alpha_s[tid] = al;
        }
        __syncthreads();

        // O = O*alpha + P @ V  (rows ty*4+i, v-cols tx*4+j)
        #pragma unroll
        for (int i = 0; i < 4; i++) {
            float al = alpha_s[ty*4+i];
            #pragma unroll
            for (int j = 0; j < 4; j++) o[i][j] *= al;
        }
        #pragma unroll
        for (int c = 0; c < KB; c++) {
            float4 v4 = *(const float4*)&Vs[c][tx*4];
            #pragma unroll
            for (int i = 0; i < 4; i++) {
                float p = Ss[ty*4+i][c];
                o[i][0] += p*v4.x; o[i][1] += p*v4.y;
                o[i][2] += p*v4.z; o[i][3] += p*v4.w;
            }
        }
    }
    __syncthreads();

    #pragma unroll
    for (int i = 0; i < 4; i++) {
        int row = ty*4 + i;
        float inv = 1.f / l_s[row];
        float4 r = make_float4(o[i][0]*inv, o[i][1]*inv, o[i][2]*inv, o[i][3]*inv);
        *(float4*)&y[((size_t)(q0+row)*BATCH + b)*DMODEL + h*HD + tx*4] = r;
    }
}

// ---------------------------------------------------------------------------
extern "C" void kernel_launch(void* const* d_in, const int* in_sizes, int n_in,
                              void* d_out, int out_size)
{
    const float* x  = (const float*)d_in[0];
    const float* Wq = (const float*)d_in[1];
    const float* bq = (const float*)d_in[2];
    const float* Wk = (const float*)d_in[3];
    const float* bk = (const float*)d_in[4];
    const float* Wv = (const float*)d_in[5];
    const float* bv = (const float*)d_in[6];
    const float* Wo = (const float*)d_in[7];
    const float* bo = (const float*)d_in[8];
    float* out = (float*)d_out;

    float *q, *k, *v, *y;
    cudaGetSymbolAddress((void**)&q, g_q);
    cudaGetSymbolAddress((void**)&k, g_k);
    cudaGetSymbolAddress((void**)&v, g_v);
    cudaGetSymbolAddress((void**)&y, g_y);

    dim3 gGrid(DMODEL/64, NTOK/64);   // (12, 64)
    gemm_bias_kernel<<<gGrid, 256>>>(x, Wq, bq, q, NTOK, DMODEL, DMODEL);
    gemm_bias_kernel<<<gGrid, 256>>>(x, Wk, bk, k, NTOK, DMODEL, DMODEL);
    gemm_bias_kernel<<<gGrid, 256>>>(x, Wv, bv, v, NTOK, DMODEL, DMODEL);

    dim3 aGrid(SEQ/64, BATCH*NH);     // (32, 24)
    attn_kernel<<<aGrid, 256>>>(q, k, v, y);

    gemm_bias_kernel<<<gGrid, 256>>>(y, Wo, bo, out, NTOK, DMODEL, DMODEL);
}

// round 3
// speedup vs baseline: 1.4961x; 1.4961x over previous
#include <cuda_runtime.h>
#include <cuda_bf16.h>
#include <cstdint>
#include <math.h>

#define SEQ     2048
#define BATCH   2
#define DMODEL  768
#define NH      12
#define HD      64
#define NTOK    (SEQ*BATCH)   // 4096
#define KB      32            // attn key tile

// ---------------------------------------------------------------------------
// Scratch (__device__ globals; allocation-free rule)
// ---------------------------------------------------------------------------
__device__ float g_q[NTOK*DMODEL];
__device__ float g_k[NTOK*DMODEL];
__device__ float g_v[NTOK*DMODEL];
__device__ float g_y[NTOK*DMODEL];
__device__ __nv_bfloat16 g_xs_hi[NTOK*DMODEL];
__device__ __nv_bfloat16 g_xs_lo[NTOK*DMODEL];
__device__ __nv_bfloat16 g_ys_hi[NTOK*DMODEL];
__device__ __nv_bfloat16 g_ys_lo[NTOK*DMODEL];
__device__ __nv_bfloat16 g_wt_hi[4*DMODEL*DMODEL];   // transposed [N][K] per weight
__device__ __nv_bfloat16 g_wt_lo[4*DMODEL*DMODEL];

// ---------------------------------------------------------------------------
// Helpers (baseline PTX only — no sm_103a-gated features)
// ---------------------------------------------------------------------------
__device__ __forceinline__ uint32_t smem_u32(const void* p) {
    uint32_t a;
    asm("{ .reg .u64 t; cvta.to.shared.u64 t, %1; cvt.u32.u64 %0, t; }" : "=r"(a) : "l"(p));
    return a;
}
#define SWZ128(o) ((o) ^ (((o) >> 3) & 0x70))

__device__ __forceinline__ void ldsm_x4(uint32_t* r, uint32_t addr) {
    asm volatile("ldmatrix.sync.aligned.m8n8.x4.shared.b16 {%0,%1,%2,%3}, [%4];"
        : "=r"(r[0]), "=r"(r[1]), "=r"(r[2]), "=r"(r[3]) : "r"(addr));
}
__device__ __forceinline__ void mma_bf16(float* c, const uint32_t* a, const uint32_t* b) {
    asm volatile("mma.sync.aligned.m16n8k16.row.col.f32.bf16.bf16.f32 "
        "{%0,%1,%2,%3}, {%4,%5,%6,%7}, {%8,%9}, {%0,%1,%2,%3};"
        : "+f"(c[0]), "+f"(c[1]), "+f"(c[2]), "+f"(c[3])
        : "r"(a[0]), "r"(a[1]), "r"(a[2]), "r"(a[3]), "r"(b[0]), "r"(b[1]));
}

// ---------------------------------------------------------------------------
// Conversion kernels
// ---------------------------------------------------------------------------
__global__ __launch_bounds__(256) void fsplit_kernel(
    const float* __restrict__ in, __nv_bfloat16* __restrict__ hi,
    __nv_bfloat16* __restrict__ lo, int n4)
{
    int i = (blockIdx.x * 256 + threadIdx.x) * 4;
    if (i >= n4 * 4) return;
    float4 f = *(const float4*)&in[i];
    __nv_bfloat16 h0 = __float2bfloat16_rn(f.x);
    __nv_bfloat16 h1 = __float2bfloat16_rn(f.y);
    __nv_bfloat16 h2 = __float2bfloat16_rn(f.z);
    __nv_bfloat16 h3 = __float2bfloat16_rn(f.w);
    __nv_bfloat16 l0 = __float2bfloat16_rn(f.x - __bfloat162float(h0));
    __nv_bfloat16 l1 = __float2bfloat16_rn(f.y - __bfloat162float(h1));
    __nv_bfloat16 l2 = __float2bfloat16_rn(f.z - __bfloat162float(h2));
    __nv_bfloat16 l3 = __float2bfloat16_rn(f.w - __bfloat162float(h3));
    reinterpret_cast<__nv_bfloat162*>(hi + i)[0] = __halves2bfloat162(h0, h1);
    reinterpret_cast<__nv_bfloat162*>(hi + i)[1] = __halves2bfloat162(h2, h3);
    reinterpret_cast<__nv_bfloat162*>(lo + i)[0] = __halves2bfloat162(l0, l1);
    reinterpret_cast<__nv_bfloat162*>(lo + i)[1] = __halves2bfloat162(l2, l3);
}

// W[K][N] (768x768) -> out[n*768 + k] bf16 hi/lo  (i.e. B^T, K-contiguous)
__global__ __launch_bounds__(256) void wtsplit_kernel(
    const float* __restrict__ W, __nv_bfloat16* __restrict__ th,
    __nv_bfloat16* __restrict__ tl)
{
    __shared__ float t[32][33];
    int n0 = blockIdx.x * 32, k0 = blockIdx.y * 32;
    int tx = threadIdx.x, ty = threadIdx.y;   // 32 x 8
    #pragma unroll
    for (int r = 0; r < 4; r++)
        t[ty + 8*r][tx] = W[(size_t)(k0 + ty + 8*r) * DMODEL + n0 + tx];
    __syncthreads();
    #pragma unroll
    for (int r = 0; r < 4; r++) {
        int row = ty + 8*r;                    // local n
        float f = t[tx][row];
        __nv_bfloat16 h = __float2bfloat16_rn(f);
        __nv_bfloat16 l = __float2bfloat16_rn(f - __bfloat162float(h));
        size_t o = (size_t)(n0 + row) * DMODEL + k0 + tx;
        th[o] = h; tl[o] = l;
    }
}

// ---------------------------------------------------------------------------
// HMMA GEMM: C[M,N] = (Ah+Al)[M,K] @ (Bh+Bl)^T + bias   (bf16-split fp32)
// A: [M][K] row-major bf16; Bt: [N][K] row-major bf16 (= col-major B).
// Tile 128x64x64; 256 threads = 8 warps (4m x 2n), warp tile 32x32.
// ---------------------------------------------------------------------------
#define S_AH 0
#define S_AL 16384
#define S_BH 32768
#define S_BL 40960

__global__ __launch_bounds__(256) void gemm_hmma_kernel(
    const __nv_bfloat16* __restrict__ Ah, const __nv_bfloat16* __restrict__ Al,
    const __nv_bfloat16* __restrict__ Bh, const __nv_bfloat16* __restrict__ Bl,
    const float* __restrict__ bias, float* __restrict__ C)
{
    __shared__ char smem[49152];
    const uint32_t sb = smem_u32(smem);
    const int tid  = threadIdx.x;
    const int lane = tid & 31, warp = tid >> 5;
    const int wm   = warp & 3, wn = warp >> 2;       // 4 x 2
    const int m0   = blockIdx.y * 128, n0 = blockIdx.x * 64;
    const int mw   = wm * 32, nw = wn * 32;

    float acc[2][4][4] = {};

    // ldmatrix per-lane tile coordinates (constant across k-chunks except k_off)
    const int a_row = (lane & 15);               // + mw + mi*16
    const int a_col8 = (lane >> 4) * 8;          // + k_off
    const int b_row = ((lane >> 4) << 3) + (lane & 7);   // + nw + half*16
    const int b_col8 = ((lane >> 3) & 1) * 8;            // + k_off

    for (int kc = 0; kc < DMODEL / 64; kc++) {
        __syncthreads();
        // A tiles: 128 rows x 128B = 1024 16B chunks (4/thread), hi+lo
        #pragma unroll
        for (int r = 0; r < 4; r++) {
            int idx = tid + 256 * r;
            int row = idx >> 3, c16 = idx & 7;
            size_t g = (size_t)(m0 + row) * DMODEL + kc * 64 + c16 * 8;
            uint32_t off = SWZ128((uint32_t)(row * 128 + c16 * 16));
            *(uint4*)(smem + S_AH + off) = *(const uint4*)&Ah[g];
            *(uint4*)(smem + S_AL + off) = *(const uint4*)&Al[g];
        }
        // B tiles: 64 rows x 128B = 512 chunks (2/thread), hi+lo
        #pragma unroll
        for (int r = 0; r < 2; r++) {
            int idx = tid + 256 * r;
            int row = idx >> 3, c16 = idx & 7;
            size_t g = (size_t)(n0 + row) * DMODEL + kc * 64 + c16 * 8;
            uint32_t off = SWZ128((uint32_t)(row * 128 + c16 * 16));
            *(uint4*)(smem + S_BH + off) = *(const uint4*)&Bh[g];
            *(uint4*)(smem + S_BL + off) = *(const uint4*)&Bl[g];
        }
        __syncthreads();

        #pragma unroll
        for (int ks = 0; ks < 4; ks++) {
            const int ko = ks * 16;
            uint32_t ah[2][4], al[2][4], bh[2][4], bl[2][4];
            #pragma unroll
            for (int mi = 0; mi < 2; mi++) {
                uint32_t off = SWZ128((uint32_t)(
                    (mw + mi * 16 + a_row) * 128 + (ko + a_col8) * 2));
                ldsm_x4(ah[mi], sb + S_AH + off);
                ldsm_x4(al[mi], sb + S_AL + off);
            }
            #pragma unroll
            for (int hf = 0; hf < 2; hf++) {
                uint32_t off = SWZ128((uint32_t)(
                    (nw + hf * 16 + b_row) * 128 + (ko + b_col8) * 2));
                ldsm_x4(bh[hf], sb + S_BH + off);
                ldsm_x4(bl[hf], sb + S_BL + off);
            }
            #pragma unroll
            for (int mi = 0; mi < 2; mi++) {
                #pragma unroll
                for (int ni = 0; ni < 4; ni++) {
                    const uint32_t* bhf = &bh[ni >> 1][(ni & 1) * 2];
                    const uint32_t* blf = &bl[ni >> 1][(ni & 1) * 2];
                    mma_bf16(acc[mi][ni], ah[mi], bhf);   // Ah*Bh
                    mma_bf16(acc[mi][ni], ah[mi], blf);   // Ah*Bl
                    mma_bf16(acc[mi][ni], al[mi], bhf);   // Al*Bh
                }
            }
        }
    }

    // Epilogue: lane holds rows (r, r+8), cols (c, c+1) per fragment
    const int er = lane >> 2, ec = (lane & 3) * 2;
    #pragma unroll
    for (int mi = 0; mi < 2; mi++) {
        #pragma unroll
        for (int ni = 0; ni < 4; ni++) {
            int row = m0 + mw + mi * 16 + er;
            int col = n0 + nw + ni * 8 + ec;
            float2 b2 = *(const float2*)&bias[col];
            float2 r0 = make_float2(acc[mi][ni][0] + b2.x, acc[mi][ni][1] + b2.y);
            float2 r1 = make_float2(acc[mi][ni][2] + b2.x, acc[mi][ni][3] + b2.y);
            *(float2*)&C[(size_t)row * DMODEL + col] = r0;
            *(float2*)&C[(size_t)(row + 8) * DMODEL + col] = r1;
        }
    }
}

// ---------------------------------------------------------------------------
// Causal flash attention (unchanged — known-good)
// ---------------------------------------------------------------------------
__global__ __launch_bounds__(256) void attn_kernel(
    const float* __restrict__ q, const float* __restrict__ k,
    const float* __restrict__ v, float* __restrict__ y)
{
    __shared__ float Qs[64][64];
    __shared__ float Kst[64][34];
    __shared__ float Vs[KB][64];
    __shared__ float Ss[64][33];
    __shared__ float m_s[64], l_s[64], alpha_s[64];

    const int tid = threadIdx.x;
    const int bx  = blockIdx.x;
    const int bh  = blockIdx.y;
    const int b   = bh / NH;
    const int h   = bh % NH;
    const int q0  = bx * 64;
    const int ty  = tid >> 4, tx = tid & 15;

    #pragma unroll
    for (int r = 0; r < 4; r++) {
        int fi  = tid + 256*r;
        int row = fi >> 4, c4 = fi & 15;
        *(float4*)&Qs[row][c4*4] =
            *(const float4*)&q[((size_t)(q0+row)*BATCH + b)*DMODEL + h*HD + c4*4];
    }
    if (tid < 64) { m_s[tid] = -1e30f; l_s[tid] = 0.f; }

    float o[4][4] = {};

    const int nkb = 2*bx + 2;
    for (int kb = 0; kb < nkb; kb++) {
        const int k0 = kb * KB;
        __syncthreads();
        #pragma unroll
        for (int r = 0; r < 2; r++) {
            int fi  = tid + 256*r;
            int tok = fi >> 4, c4 = fi & 15;
            size_t gbase = ((size_t)(k0+tok)*BATCH + b)*DMODEL + h*HD + c4*4;
            float4 kv = *(const float4*)&k[gbase];
            Kst[c4*4+0][tok] = kv.x;
            Kst[c4*4+1][tok] = kv.y;
            Kst[c4*4+2][tok] = kv.z;
            Kst[c4*4+3][tok] = kv.w;
            *(float4*)&Vs[tok][c4*4] = *(const float4*)&v[gbase];
        }
        __syncthreads();

        float sc[4][2] = {};
        #pragma unroll
        for (int d = 0; d < 64; d += 4) {
            float2 k0v = *(const float2*)&Kst[d+0][tx*2];
            float2 k1v = *(const float2*)&Kst[d+1][tx*2];
            float2 k2v = *(const float2*)&Kst[d+2][tx*2];
            float2 k3v = *(const float2*)&Kst[d+3][tx*2];
            #pragma unroll
            for (int i = 0; i < 4; i++) {
                float4 q4 = *(const float4*)&Qs[ty*4+i][d];
                sc[i][0] += q4.x*k0v.x + q4.y*k1v.x + q4.z*k2v.x + q4.w*k3v.x;
                sc[i][1] += q4.x*k0v.y + q4.y*k1v.y + q4.z*k2v.y + q4.w*k3v.y;
            }
        }
        #pragma unroll
        for (int i = 0; i < 4; i++) {
            int qs = q0 + ty*4 + i;
            #pragma unroll
            for (int j = 0; j < 2; j++) {
                int ks = k0 + tx*2 + j;
                Ss[ty*4+i][tx*2+j] = (ks <= qs) ? sc[i][j]*0.125f : -1e30f;
            }
        }
        __syncthreads();

        if (tid < 64) {
            float mo = m_s[tid];
            float rm = mo;
            #pragma unroll
            for (int c = 0; c < KB; c++) rm = fmaxf(rm, Ss[tid][c]);
            float al  = __expf(mo - rm);
            float sum = 0.f;
            #pragma unroll
            for (int c = 0; c < KB; c++) {
                float p = __expf(Ss[tid][c] - rm);
                Ss[tid][c] = p;
                sum += p;
            }
            m_s[tid]     = rm;
            l_s[tid]     = l_s[tid]*al + sum;
            alpha_s[tid] = al;
        }
        __syncthreads();

        #pragma unroll
        for (int i = 0; i < 4; i++) {
            float al = alpha_s[ty*4+i];
            #pragma unroll
            for (int j = 0; j < 4; j++) o[i][j] *= al;
        }
        #pragma unroll
        for (int c = 0; c < KB; c++) {
            float4 v4 = *(const float4*)&Vs[c][tx*4];
            #pragma unroll
            for (int i = 0; i < 4; i++) {
                float p = Ss[ty*4+i][c];
                o[i][0] += p*v4.x; o[i][1] += p*v4.y;
                o[i][2] += p*v4.z; o[i][3] += p*v4.w;
            }
        }
    }
    __syncthreads();

    #pragma unroll
    for (int i = 0; i < 4; i++) {
        int row = ty*4 + i;
        float inv = 1.f / l_s[row];
        float4 r = make_float4(o[i][0]*inv, o[i][1]*inv, o[i][2]*inv, o[i][3]*inv);
        *(float4*)&y[((size_t)(q0+row)*BATCH + b)*DMODEL + h*HD + tx*4] = r;
    }
}

// ---------------------------------------------------------------------------
extern "C" void kernel_launch(void* const* d_in, const int* in_sizes, int n_in,
                              void* d_out, int out_size)
{
    const float* x  = (const float*)d_in[0];
    const float* Wq = (const float*)d_in[1];
    const float* bq = (const float*)d_in[2];
    const float* Wk = (const float*)d_in[3];
    const float* bk = (const float*)d_in[4];
    const float* Wv = (const float*)d_in[5];
    const float* bv = (const float*)d_in[6];
    const float* Wo = (const float*)d_in[7];
    const float* bo = (const float*)d_in[8];
    float* out = (float*)d_out;

    float *q, *k, *v, *y;
    cudaGetSymbolAddress((void**)&q, g_q);
    cudaGetSymbolAddress((void**)&k, g_k);
    cudaGetSymbolAddress((void**)&v, g_v);
    cudaGetSymbolAddress((void**)&y, g_y);
    __nv_bfloat16 *xs_hi, *xs_lo, *ys_hi, *ys_lo, *wt_hi, *wt_lo;
    cudaGetSymbolAddress((void**)&xs_hi, g_xs_hi);
    cudaGetSymbolAddress((void**)&xs_lo, g_xs_lo);
    cudaGetSymbolAddress((void**)&ys_hi, g_ys_hi);
    cudaGetSymbolAddress((void**)&ys_lo, g_ys_lo);
    cudaGetSymbolAddress((void**)&wt_hi, g_wt_hi);
    cudaGetSymbolAddress((void**)&wt_lo, g_wt_lo);

    const size_t WSZ = (size_t)DMODEL * DMODEL;

    // Weight transpose+split (4 weights)
    dim3 wtGrid(DMODEL/32, DMODEL/32), wtBlk(32, 8);
    wtsplit_kernel<<<wtGrid, wtBlk>>>(Wq, wt_hi + 0*WSZ, wt_lo + 0*WSZ);
    wtsplit_kernel<<<wtGrid, wtBlk>>>(Wk, wt_hi + 1*WSZ, wt_lo + 1*WSZ);
    wtsplit_kernel<<<wtGrid, wtBlk>>>(Wv, wt_hi + 2*WSZ, wt_lo + 2*WSZ);
    wtsplit_kernel<<<wtGrid, wtBlk>>>(Wo, wt_hi + 3*WSZ, wt_lo + 3*WSZ);

    // x split
    int n4 = NTOK * DMODEL / 4;
    fsplit_kernel<<<n4 / 256, 256>>>(x, xs_hi, xs_lo, n4);

    // QKV projections (HMMA)
    dim3 gGrid(DMODEL/64, NTOK/128);   // (12, 32)
    gemm_hmma_kernel<<<gGrid, 256>>>(xs_hi, xs_lo, wt_hi + 0*WSZ, wt_lo + 0*WSZ, bq, q);
    gemm_hmma_kernel<<<gGrid, 256>>>(xs_hi, xs_lo, wt_hi + 1*WSZ, wt_lo + 1*WSZ, bk, k);
    gemm_hmma_kernel<<<gGrid, 256>>>(xs_hi, xs_lo, wt_hi + 2*WSZ, wt_lo + 2*WSZ, bv, v);

    // Attention
    dim3 aGrid(SEQ/64, BATCH*NH);
    attn_kernel<<<aGrid, 256>>>(q, k, v, y);

    // y split + output projection
    fsplit_kernel<<<n4 / 256, 256>>>(y, ys_hi, ys_lo, n4);
    gemm_hmma_kernel<<<gGrid, 256>>>(ys_hi, ys_lo, wt_hi + 3*WSZ, wt_lo + 3*WSZ, bo, out);
}

// round 4
// speedup vs baseline: 2.7845x; 1.8612x over previous
#include <cuda_runtime.h>
#include <cuda_bf16.h>
#include <cstdint>
#include <math.h>

#define SEQ     2048
#define BATCH   2
#define DMODEL  768
#define NH      12
#define HD      64
#define NTOK    (SEQ*BATCH)   // 4096

// ---------------------------------------------------------------------------
// Scratch (__device__ globals; allocation-free rule)
// ---------------------------------------------------------------------------
__device__ __nv_bfloat16 g_xs_hi[NTOK*DMODEL];
__device__ __nv_bfloat16 g_xs_lo[NTOK*DMODEL];
__device__ __nv_bfloat16 g_qh[NTOK*DMODEL];
__device__ __nv_bfloat16 g_ql[NTOK*DMODEL];
__device__ __nv_bfloat16 g_kh[NTOK*DMODEL];
__device__ __nv_bfloat16 g_kl[NTOK*DMODEL];
__device__ __nv_bfloat16 g_vh[NTOK*DMODEL];
__device__ __nv_bfloat16 g_vl[NTOK*DMODEL];
__device__ __nv_bfloat16 g_ys_hi[NTOK*DMODEL];
__device__ __nv_bfloat16 g_ys_lo[NTOK*DMODEL];
__device__ __nv_bfloat16 g_wt_hi[4*DMODEL*DMODEL];   // transposed [N][K] per weight
__device__ __nv_bfloat16 g_wt_lo[4*DMODEL*DMODEL];

// ---------------------------------------------------------------------------
// Helpers (baseline PTX only — nothing sm_103a-gated)
// ---------------------------------------------------------------------------
__device__ __forceinline__ uint32_t smem_u32(const void* p) {
    uint32_t a;
    asm("{ .reg .u64 t; cvta.to.shared.u64 t, %1; cvt.u32.u64 %0, t; }" : "=r"(a) : "l"(p));
    return a;
}
#define SWZ128(o) ((o) ^ (((o) >> 3) & 0x70))

__device__ __forceinline__ void ldsm_x4(uint32_t* r, uint32_t addr) {
    asm volatile("ldmatrix.sync.aligned.m8n8.x4.shared.b16 {%0,%1,%2,%3}, [%4];"
        : "=r"(r[0]), "=r"(r[1]), "=r"(r[2]), "=r"(r[3]) : "r"(addr));
}
__device__ __forceinline__ uint32_t movm_t(uint32_t s) {
    uint32_t d;
    asm volatile("movmatrix.sync.aligned.m8n8.trans.b16 %0, %1;" : "=r"(d) : "r"(s));
    return d;
}
__device__ __forceinline__ void mma_bf16(float* c, const uint32_t* a, const uint32_t* b) {
    asm volatile("mma.sync.aligned.m16n8k16.row.col.f32.bf16.bf16.f32 "
        "{%0,%1,%2,%3}, {%4,%5,%6,%7}, {%8,%9}, {%0,%1,%2,%3};"
        : "+f"(c[0]), "+f"(c[1]), "+f"(c[2]), "+f"(c[3])
        : "r"(a[0]), "r"(a[1]), "r"(a[2]), "r"(a[3]), "r"(b[0]), "r"(b[1]));
}
__device__ __forceinline__ void split2(float a, float b, uint32_t& hi, uint32_t& lo) {
    __nv_bfloat162 h = __floats2bfloat162_rn(a, b);
    __nv_bfloat162 l = __floats2bfloat162_rn(a - __bfloat162float(h.x),
                                             b - __bfloat162float(h.y));
    hi = *reinterpret_cast<uint32_t*>(&h);
    lo = *reinterpret_cast<uint32_t*>(&l);
}

// ---------------------------------------------------------------------------
// Conversion kernels
// ---------------------------------------------------------------------------
__global__ __launch_bounds__(256) void fsplit_kernel(
    const float* __restrict__ in, __nv_bfloat16* __restrict__ hi,
    __nv_bfloat16* __restrict__ lo, int n4)
{
    int i = (blockIdx.x * 256 + threadIdx.x) * 4;
    if (i >= n4 * 4) return;
    float4 f = *(const float4*)&in[i];
    uint32_t h0, l0, h1, l1;
    split2(f.x, f.y, h0, l0);
    split2(f.z, f.w, h1, l1);
    reinterpret_cast<uint32_t*>(hi + i)[0] = h0;
    reinterpret_cast<uint32_t*>(hi + i)[1] = h1;
    reinterpret_cast<uint32_t*>(lo + i)[0] = l0;
    reinterpret_cast<uint32_t*>(lo + i)[1] = l1;
}

// W[K][N] (768x768) -> out[n*768 + k] bf16 hi/lo  (i.e. B^T, K-contiguous)
__global__ __launch_bounds__(256) void wtsplit_kernel(
    const float* __restrict__ W, __nv_bfloat16* __restrict__ th,
    __nv_bfloat16* __restrict__ tl)
{
    __shared__ float t[32][33];
    int n0 = blockIdx.x * 32, k0 = blockIdx.y * 32;
    int tx = threadIdx.x, ty = threadIdx.y;   // 32 x 8
    #pragma unroll
    for (int r = 0; r < 4; r++)
        t[ty + 8*r][tx] = W[(size_t)(k0 + ty + 8*r) * DMODEL + n0 + tx];
    __syncthreads();
    #pragma unroll
    for (int r = 0; r < 4; r++) {
        int row = ty + 8*r;                    // local n
        float f = t[tx][row];
        __nv_bfloat16 h = __float2bfloat16_rn(f);
        __nv_bfloat16 l = __float2bfloat16_rn(f - __bfloat162float(h));
        size_t o = (size_t)(n0 + row) * DMODEL + k0 + tx;
        th[o] = h; tl[o] = l;
    }
}

// ---------------------------------------------------------------------------
// HMMA GEMM: C = (Ah+Al)[M,K] @ (Bh+Bl)^T + bias   (bf16-split fp32)
// mode 0: fp32 out Cf;  mode 1: bf16 hi/lo out (Oh, Ol)
// Tile 128x64x64; 256 threads = 8 warps (4m x 2n), warp tile 32x32.
// ---------------------------------------------------------------------------
#define S_AH 0
#define S_AL 16384
#define S_BH 32768
#define S_BL 40960

__global__ __launch_bounds__(256) void gemm_hmma_kernel(
    const __nv_bfloat16* __restrict__ Ah, const __nv_bfloat16* __restrict__ Al,
    const __nv_bfloat16* __restrict__ Bh, const __nv_bfloat16* __restrict__ Bl,
    const float* __restrict__ bias, float* __restrict__ Cf,
    __nv_bfloat16* __restrict__ Oh, __nv_bfloat16* __restrict__ Ol, int mode)
{
    __shared__ char smem[49152];
    const uint32_t sb = smem_u32(smem);
    const int tid  = threadIdx.x;
    const int lane = tid & 31, warp = tid >> 5;
    const int wm   = warp & 3, wn = warp >> 2;       // 4 x 2
    const int m0   = blockIdx.y * 128, n0 = blockIdx.x * 64;
    const int mw   = wm * 32, nw = wn * 32;

    float acc[2][4][4] = {};

    const int a_row = (lane & 15);
    const int a_col8 = (lane >> 4) * 8;
    const int b_row = ((lane >> 4) << 3) + (lane & 7);
    const int b_col8 = ((lane >> 3) & 1) * 8;

    for (int kc = 0; kc < DMODEL / 64; kc++) {
        __syncthreads();
        #pragma unroll
        for (int r = 0; r < 4; r++) {
            int idx = tid + 256 * r;
            int row = idx >> 3, c16 = idx & 7;
            size_t g = (size_t)(m0 + row) * DMODEL + kc * 64 + c16 * 8;
            uint32_t off = SWZ128((uint32_t)(row * 128 + c16 * 16));
            *(uint4*)(smem + S_AH + off) = *(const uint4*)&Ah[g];
            *(uint4*)(smem + S_AL + off) = *(const uint4*)&Al[g];
        }
        #pragma unroll
        for (int r = 0; r < 2; r++) {
            int idx = tid + 256 * r;
            int row = idx >> 3, c16 = idx & 7;
            size_t g = (size_t)(n0 + row) * DMODEL + kc * 64 + c16 * 8;
            uint32_t off = SWZ128((uint32_t)(row * 128 + c16 * 16));
            *(uint4*)(smem + S_BH + off) = *(const uint4*)&Bh[g];
            *(uint4*)(smem + S_BL + off) = *(const uint4*)&Bl[g];
        }
        __syncthreads();

        #pragma unroll
        for (int ks = 0; ks < 4; ks++) {
            const int ko = ks * 16;
            uint32_t ah[2][4], al[2][4], bh[2][4], bl[2][4];
            #pragma unroll
            for (int mi = 0; mi < 2; mi++) {
                uint32_t off = SWZ128((uint32_t)(
                    (mw + mi * 16 + a_row) * 128 + (ko + a_col8) * 2));
                ldsm_x4(ah[mi], sb + S_AH + off);
                ldsm_x4(al[mi], sb + S_AL + off);
            }
            #pragma unroll
            for (int hf = 0; hf < 2; hf++) {
                uint32_t off = SWZ128((uint32_t)(
                    (nw + hf * 16 + b_row) * 128 + (ko + b_col8) * 2));
                ldsm_x4(bh[hf], sb + S_BH + off);
                ldsm_x4(bl[hf], sb + S_BL + off);
            }
            #pragma unroll
            for (int mi = 0; mi < 2; mi++) {
                #pragma unroll
                for (int ni = 0; ni < 4; ni++) {
                    const uint32_t* bhf = &bh[ni >> 1][(ni & 1) * 2];
                    const uint32_t* blf = &bl[ni >> 1][(ni & 1) * 2];
                    mma_bf16(acc[mi][ni], ah[mi], bhf);
                    mma_bf16(acc[mi][ni], ah[mi], blf);
                    mma_bf16(acc[mi][ni], al[mi], bhf);
                }
            }
        }
    }

    const int er = lane >> 2, ec = (lane & 3) * 2;
    #pragma unroll
    for (int mi = 0; mi < 2; mi++) {
        #pragma unroll
        for (int ni = 0; ni < 4; ni++) {
            int row = m0 + mw + mi * 16 + er;
            int col = n0 + nw + ni * 8 + ec;
            float2 b2 = *(const float2*)&bias[col];
            float v0 = acc[mi][ni][0] + b2.x, v1 = acc[mi][ni][1] + b2.y;
            float v2 = acc[mi][ni][2] + b2.x, v3 = acc[mi][ni][3] + b2.y;
            if (mode == 0) {
                *(float2*)&Cf[(size_t)row * DMODEL + col] = make_float2(v0, v1);
                *(float2*)&Cf[(size_t)(row + 8) * DMODEL + col] = make_float2(v2, v3);
            } else {
                uint32_t h0, l0, h1, l1;
                split2(v0, v1, h0, l0);
                split2(v2, v3, h1, l1);
                *(uint32_t*)&Oh[(size_t)row * DMODEL + col] = h0;
                *(uint32_t*)&Ol[(size_t)row * DMODEL + col] = l0;
                *(uint32_t*)&Oh[(size_t)(row + 8) * DMODEL + col] = h1;
                *(uint32_t*)&Ol[(size_t)(row + 8) * DMODEL + col] = l1;
            }
        }
    }
}

// ---------------------------------------------------------------------------
// Tensor-core causal flash attention.
// CTA: 64 q-rows x one (b,h). 128 threads = 4 warps, 16 q-rows each.
// Key tiles of 64. bf16 hi/lo split everywhere (3-MMA). V^T via movmatrix.
// Writes y directly as bf16 hi/lo.
// ---------------------------------------------------------------------------
#define AQ_H 0
#define AQ_L 8192
#define AK_H 16384
#define AK_L 24576
#define AV_H 32768
#define AV_L 40960

__global__ __launch_bounds__(128) void attn_tc_kernel(
    const __nv_bfloat16* __restrict__ qh, const __nv_bfloat16* __restrict__ ql,
    const __nv_bfloat16* __restrict__ kh, const __nv_bfloat16* __restrict__ kl,
    const __nv_bfloat16* __restrict__ vh, const __nv_bfloat16* __restrict__ vl,
    __nv_bfloat16* __restrict__ yh, __nv_bfloat16* __restrict__ yl)
{
    __shared__ char smem[49152];
    const uint32_t sb = smem_u32(smem);
    const int tid  = threadIdx.x;
    const int lane = tid & 31, warp = tid >> 5;
    const int bx   = gridDim.x - 1 - blockIdx.x;      // heavy tiles first
    const int bh_  = blockIdx.y;
    const int b    = bh_ / NH, h = bh_ % NH;
    const int q0   = bx * 64;
    const int mw   = warp * 16;

    const int a_row  = lane & 15;
    const int a_col8 = (lane >> 4) * 8;
    const int b_row  = ((lane >> 4) << 3) + (lane & 7);
    const int b_col8 = ((lane >> 3) & 1) * 8;
    const int er = lane >> 2, ec = (lane & 3) * 2;

    // --- load Q tile (hi/lo) into smem ---
    #pragma unroll
    for (int r = 0; r < 4; r++) {
        int idx = tid + 128 * r;
        int row = idx >> 3, c16 = idx & 7;
        size_t g = (size_t)((q0 + row) * BATCH + b) * DMODEL + h * HD + c16 * 8;
        uint32_t off = SWZ128((uint32_t)(row * 128 + c16 * 16));
        *(uint4*)(smem + AQ_H + off) = *(const uint4*)&qh[g];
        *(uint4*)(smem + AQ_L + off) = *(const uint4*)&ql[g];
    }
    __syncthreads();

    // --- Q fragments (held all kernel) ---
    uint32_t aqh[4][4], aql[4][4];
    #pragma unroll
    for (int ks = 0; ks < 4; ks++) {
        uint32_t off = SWZ128((uint32_t)((mw + a_row) * 128 + (ks * 16 + a_col8) * 2));
        ldsm_x4(aqh[ks], sb + AQ_H + off);
        ldsm_x4(aql[ks], sb + AQ_L + off);
    }

    float o[8][4] = {};
    float m_[2] = {-1e30f, -1e30f};
    float l_[2] = {0.f, 0.f};

    const int ntiles = bx + 1;
    for (int kb = 0; kb < ntiles; kb++) {
        const int k0 = kb * 64;
        __syncthreads();
        // --- load K and V tiles (hi/lo) ---
        #pragma unroll
        for (int r = 0; r < 4; r++) {
            int idx = tid + 128 * r;
            int row = idx >> 3, c16 = idx & 7;
            size_t g = (size_t)((k0 + row) * BATCH + b) * DMODEL + h * HD + c16 * 8;
            uint32_t off = SWZ128((uint32_t)(row * 128 + c16 * 16));
            *(uint4*)(smem + AK_H + off) = *(const uint4*)&kh[g];
            *(uint4*)(smem + AK_L + off) = *(const uint4*)&kl[g];
            *(uint4*)(smem + AV_H + off) = *(const uint4*)&vh[g];
            *(uint4*)(smem + AV_L + off) = *(const uint4*)&vl[g];
        }
        __syncthreads();

        // --- S = Q @ K^T (3-MMA split) ---
        float s[8][4] = {};
        #pragma unroll
        for (int ks = 0; ks < 4; ks++) {
            uint32_t kbh[4][4], kbl[4][4];
            #pragma unroll
            for (int nf2 = 0; nf2 < 4; nf2++) {
                uint32_t off = SWZ128((uint32_t)(
                    (nf2 * 16 + b_row) * 128 + (ks * 16 + b_col8) * 2));
                ldsm_x4(kbh[nf2], sb + AK_H + off);
                ldsm_x4(kbl[nf2], sb + AK_L + off);
            }
            #pragma unroll
            for (int nf = 0; nf < 8; nf++) {
                const uint32_t* Bh = &kbh[nf >> 1][(nf & 1) * 2];
                const uint32_t* Bl = &kbl[nf >> 1][(nf & 1) * 2];
                mma_bf16(s[nf], aqh[ks], Bh);
                mma_bf16(s[nf], aqh[ks], Bl);
                mma_bf16(s[nf], aql[ks], Bh);
            }
        }

        // --- scale + causal mask (diagonal tile only) ---
        if (kb == ntiles - 1) {
            #pragma unroll
            for (int nf = 0; nf < 8; nf++) {
                #pragma unroll
                for (int c = 0; c < 4; c++) {
                    int key = k0 + nf * 8 + ec + (c & 1);
                    int qr  = q0 + mw + er + (c >> 1) * 8;
                    s[nf][c] = (key <= qr) ? s[nf][c] * 0.125f : -1e30f;
                }
            }
        } else {
            #pragma unroll
            for (int nf = 0; nf < 8; nf++)
                #pragma unroll
                for (int c = 0; c < 4; c++) s[nf][c] *= 0.125f;
        }

        // --- online softmax (register, quad shuffles) ---
        float mx0 = -1e30f, mx1 = -1e30f;
        #pragma unroll
        for (int nf = 0; nf < 8; nf++) {
            mx0 = fmaxf(mx0, fmaxf(s[nf][0], s[nf][1]));
            mx1 = fmaxf(mx1, fmaxf(s[nf][2], s[nf][3]));
        }
        mx0 = fmaxf(mx0, __shfl_xor_sync(0xffffffffu, mx0, 1));
        mx0 = fmaxf(mx0, __shfl_xor_sync(0xffffffffu, mx0, 2));
        mx1 = fmaxf(mx1, __shfl_xor_sync(0xffffffffu, mx1, 1));
        mx1 = fmaxf(mx1, __shfl_xor_sync(0xffffffffu, mx1, 2));
        float mn0 = fmaxf(m_[0], mx0), mn1 = fmaxf(m_[1], mx1);
        float al0 = __expf(m_[0] - mn0), al1 = __expf(m_[1] - mn1);
        m_[0] = mn0; m_[1] = mn1;
        float sum0 = 0.f, sum1 = 0.f;
        #pragma unroll
        for (int nf = 0; nf < 8; nf++) {
            s[nf][0] = __expf(s[nf][0] - mn0); sum0 += s[nf][0];
            s[nf][1] = __expf(s[nf][1] - mn0); sum0 += s[nf][1];
            s[nf][2] = __expf(s[nf][2] - mn1); sum1 += s[nf][2];
            s[nf][3] = __expf(s[nf][3] - mn1); sum1 += s[nf][3];
        }
        sum0 += __shfl_xor_sync(0xffffffffu, sum0, 1);
        sum0 += __shfl_xor_sync(0xffffffffu, sum0, 2);
        sum1 += __shfl_xor_sync(0xffffffffu, sum1, 1);
        sum1 += __shfl_xor_sync(0xffffffffu, sum1, 2);
        l_[0] = l_[0] * al0 + sum0;
        l_[1] = l_[1] * al1 + sum1;
        #pragma unroll
        for (int df = 0; df < 8; df++) {
            o[df][0] *= al0; o[df][1] *= al0;
            o[df][2] *= al1; o[df][3] *= al1;
        }

        // --- O += P @ V (P split hi/lo; V^T via movmatrix) ---
        #pragma unroll
        for (int ks = 0; ks < 4; ks++) {
            uint32_t aph[4], apl[4];
            split2(s[2*ks][0],   s[2*ks][1],   aph[0], apl[0]);
            split2(s[2*ks][2],   s[2*ks][3],   aph[1], apl[1]);
            split2(s[2*ks+1][0], s[2*ks+1][1], aph[2], apl[2]);
            split2(s[2*ks+1][2], s[2*ks+1][3], aph[3], apl[3]);
            #pragma unroll
            for (int df2 = 0; df2 < 4; df2++) {
                uint32_t off = SWZ128((uint32_t)(
                    (ks * 16 + a_row) * 128 + (df2 * 16 + a_col8) * 2));
                uint32_t rvh[4], rvl[4];
                ldsm_x4(rvh, sb + AV_H + off);
                ldsm_x4(rvl, sb + AV_L + off);
                uint32_t tvh[4], tvl[4];
                #pragma unroll
                for (int i = 0; i < 4; i++) { tvh[i] = movm_t(rvh[i]); tvl[i] = movm_t(rvl[i]); }
                mma_bf16(o[2*df2],   aph, &tvh[0]);
                mma_bf16(o[2*df2],   aph, &tvl[0]);
                mma_bf16(o[2*df2],   apl, &tvh[0]);
                mma_bf16(o[2*df2+1], aph, &tvh[2]);
                mma_bf16(o[2*df2+1], aph, &tvl[2]);
                mma_bf16(o[2*df2+1], apl, &tvh[2]);
            }
        }
    }

    // --- epilogue: normalize, split, store bf16 hi/lo ---
    float inv0 = 1.f / l_[0], inv1 = 1.f / l_[1];
    int tok0 = (q0 + mw + er) * BATCH + b;
    int tok1 = tok0 + 8 * BATCH;
    #pragma unroll
    for (int df = 0; df < 8; df++) {
        int col = h * HD + df * 8 + ec;
        uint32_t h0, l0, h1, l1;
        split2(o[df][0] * inv0, o[df][1] * inv0, h0, l0);
        split2(o[df][2] * inv1, o[df][3] * inv1, h1, l1);
        *(uint32_t*)&yh[(size_t)tok0 * DMODEL + col] = h0;
        *(uint32_t*)&yl[(size_t)tok0 * DMODEL + col] = l0;
        *(uint32_t*)&yh[(size_t)tok1 * DMODEL + col] = h1;
        *(uint32_t*)&yl[(size_t)tok1 * DMODEL + col] = l1;
    }
}

// ---------------------------------------------------------------------------
extern "C" void kernel_launch(void* const* d_in, const int* in_sizes, int n_in,
                              void* d_out, int out_size)
{
    const float* x  = (const float*)d_in[0];
    const float* Wq = (const float*)d_in[1];
    const float* bq = (const float*)d_in[2];
    const float* Wk = (const float*)d_in[3];
    const float* bk = (const float*)d_in[4];
    const float* Wv = (const float*)d_in[5];
    const float* bv = (const float*)d_in[6];
    const float* Wo = (const float*)d_in[7];
    const float* bo = (const float*)d_in[8];
    float* out = (float*)d_out;

    __nv_bfloat16 *xs_hi, *xs_lo, *qh, *ql, *kh, *kl, *vh, *vl, *ys_hi, *ys_lo, *wt_hi, *wt_lo;
    cudaGetSymbolAddress((void**)&xs_hi, g_xs_hi);
    cudaGetSymbolAddress((void**)&xs_lo, g_xs_lo);
    cudaGetSymbolAddress((void**)&qh, g_qh);
    cudaGetSymbolAddress((void**)&ql, g_ql);
    cudaGetSymbolAddress((void**)&kh, g_kh);
    cudaGetSymbolAddress((void**)&kl, g_kl);
    cudaGetSymbolAddress((void**)&vh, g_vh);
    cudaGetSymbolAddress((void**)&vl, g_vl);
    cudaGetSymbolAddress((void**)&ys_hi, g_ys_hi);
    cudaGetSymbolAddress((void**)&ys_lo, g_ys_lo);
    cudaGetSymbolAddress((void**)&wt_hi, g_wt_hi);
    cudaGetSymbolAddress((void**)&wt_lo, g_wt_lo);

    const size_t WSZ = (size_t)DMODEL * DMODEL;

    dim3 wtGrid(DMODEL/32, DMODEL/32), wtBlk(32, 8);
    wtsplit_kernel<<<wtGrid, wtBlk>>>(Wq, wt_hi + 0*WSZ, wt_lo + 0*WSZ);
    wtsplit_kernel<<<wtGrid, wtBlk>>>(Wk, wt_hi + 1*WSZ, wt_lo + 1*WSZ);
    wtsplit_kernel<<<wtGrid, wtBlk>>>(Wv, wt_hi + 2*WSZ, wt_lo + 2*WSZ);
    wtsplit_kernel<<<wtGrid, wtBlk>>>(Wo, wt_hi + 3*WSZ, wt_lo + 3*WSZ);

    int n4 = NTOK * DMODEL / 4;
    fsplit_kernel<<<n4 / 256, 256>>>(x, xs_hi, xs_lo, n4);

    dim3 gGrid(DMODEL/64, NTOK/128);   // (12, 32)
    gemm_hmma_kernel<<<gGrid, 256>>>(xs_hi, xs_lo, wt_hi + 0*WSZ, wt_lo + 0*WSZ, bq,
                                     nullptr, qh, ql, 1);
    gemm_hmma_kernel<<<gGrid, 256>>>(xs_hi, xs_lo, wt_hi + 1*WSZ, wt_lo + 1*WSZ, bk,
                                     nullptr, kh, kl, 1);
    gemm_hmma_kernel<<<gGrid, 256>>>(xs_hi, xs_lo, wt_hi + 2*WSZ, wt_lo + 2*WSZ, bv,
                                     nullptr, vh, vl, 1);

    dim3 aGrid(SEQ/64, BATCH*NH);      // (32, 24)
    attn_tc_kernel<<<aGrid, 128>>>(qh, ql, kh, kl, vh, vl, ys_hi, ys_lo);

    gemm_hmma_kernel<<<gGrid, 256>>>(ys_hi, ys_lo, wt_hi + 3*WSZ, wt_lo + 3*WSZ, bo,
                                     out, nullptr, nullptr, 0);
}

// round 5
// speedup vs baseline: 3.3436x; 1.2008x over previous
#include <cuda_runtime.h>
#include <cuda_bf16.h>
#include <cstdint>
#include <math.h>

#define SEQ     2048
#define BATCH   2
#define DMODEL  768
#define NH      12
#define HD      64
#define NTOK    (SEQ*BATCH)   // 4096
#define NQKV    (3*DMODEL)    // 2304

// ---------------------------------------------------------------------------
// Scratch (__device__ globals; allocation-free rule)
// ---------------------------------------------------------------------------
__device__ __nv_bfloat16 g_xs_hi[NTOK*DMODEL];
__device__ __nv_bfloat16 g_xs_lo[NTOK*DMODEL];
__device__ __nv_bfloat16 g_qkvh[NTOK*NQKV];
__device__ __nv_bfloat16 g_qkvl[NTOK*NQKV];
__device__ __nv_bfloat16 g_ys_hi[NTOK*DMODEL];
__device__ __nv_bfloat16 g_ys_lo[NTOK*DMODEL];
__device__ __nv_bfloat16 g_wt_hi[4*DMODEL*DMODEL];   // transposed [N][K]; q,k,v,o slabs
__device__ __nv_bfloat16 g_wt_lo[4*DMODEL*DMODEL];
__device__ float g_bqkv[NQKV];

// ---------------------------------------------------------------------------
// Helpers (baseline PTX only — nothing sm_103a-gated)
// ---------------------------------------------------------------------------
__device__ __forceinline__ uint32_t smem_u32(const void* p) {
    uint32_t a;
    asm("{ .reg .u64 t; cvta.to.shared.u64 t, %1; cvt.u32.u64 %0, t; }" : "=r"(a) : "l"(p));
    return a;
}
#define SWZ128(o) ((o) ^ (((o) >> 3) & 0x70))

__device__ __forceinline__ void ldsm_x4(uint32_t* r, uint32_t addr) {
    asm volatile("ldmatrix.sync.aligned.m8n8.x4.shared.b16 {%0,%1,%2,%3}, [%4];"
        : "=r"(r[0]), "=r"(r[1]), "=r"(r[2]), "=r"(r[3]) : "r"(addr));
}
__device__ __forceinline__ uint32_t movm_t(uint32_t s) {
    uint32_t d;
    asm volatile("movmatrix.sync.aligned.m8n8.trans.b16 %0, %1;" : "=r"(d) : "r"(s));
    return d;
}
__device__ __forceinline__ void mma_bf16(float* c, const uint32_t* a, const uint32_t* b) {
    asm volatile("mma.sync.aligned.m16n8k16.row.col.f32.bf16.bf16.f32 "
        "{%0,%1,%2,%3}, {%4,%5,%6,%7}, {%8,%9}, {%0,%1,%2,%3};"
        : "+f"(c[0]), "+f"(c[1]), "+f"(c[2]), "+f"(c[3])
        : "r"(a[0]), "r"(a[1]), "r"(a[2]), "r"(a[3]), "r"(b[0]), "r"(b[1]));
}
__device__ __forceinline__ void split2(float a, float b, uint32_t& hi, uint32_t& lo) {
    __nv_bfloat162 h = __floats2bfloat162_rn(a, b);
    __nv_bfloat162 l = __floats2bfloat162_rn(a - __bfloat162float(h.x),
                                             b - __bfloat162float(h.y));
    hi = *reinterpret_cast<uint32_t*>(&h);
    lo = *reinterpret_cast<uint32_t*>(&l);
}
__device__ __forceinline__ void cp16(uint32_t saddr, const void* g) {
    asm volatile("cp.async.cg.shared.global [%0], [%1], 16;" :: "r"(saddr), "l"(g) : "memory");
}
__device__ __forceinline__ void cp_commit() {
    asm volatile("cp.async.commit_group;" ::: "memory");
}
template<int N> __device__ __forceinline__ void cp_wait() {
    asm volatile("cp.async.wait_group %0;" :: "n"(N) : "memory");
}

// ---------------------------------------------------------------------------
// Conversion kernels
// ---------------------------------------------------------------------------
__global__ __launch_bounds__(256) void fsplit_kernel(
    const float* __restrict__ in, __nv_bfloat16* __restrict__ hi,
    __nv_bfloat16* __restrict__ lo, int n4)
{
    int i = (blockIdx.x * 256 + threadIdx.x) * 4;
    if (i >= n4 * 4) return;
    float4 f = *(const float4*)&in[i];
    uint32_t h0, l0, h1, l1;
    split2(f.x, f.y, h0, l0);
    split2(f.z, f.w, h1, l1);
    reinterpret_cast<uint32_t*>(hi + i)[0] = h0;
    reinterpret_cast<uint32_t*>(hi + i)[1] = h1;
    reinterpret_cast<uint32_t*>(lo + i)[0] = l0;
    reinterpret_cast<uint32_t*>(lo + i)[1] = l1;
}

// W[K][N] (768x768) -> out[n*768 + k] bf16 hi/lo  (B^T, K-contiguous)
__global__ __launch_bounds__(256) void wtsplit_kernel(
    const float* __restrict__ W, __nv_bfloat16* __restrict__ th,
    __nv_bfloat16* __restrict__ tl)
{
    __shared__ float t[32][33];
    int n0 = blockIdx.x * 32, k0 = blockIdx.y * 32;
    int tx = threadIdx.x, ty = threadIdx.y;   // 32 x 8
    #pragma unroll
    for (int r = 0; r < 4; r++)
        t[ty + 8*r][tx] = W[(size_t)(k0 + ty + 8*r) * DMODEL + n0 + tx];
    __syncthreads();
    #pragma unroll
    for (int r = 0; r < 4; r++) {
        int row = ty + 8*r;
        float f = t[tx][row];
        __nv_bfloat16 h = __float2bfloat16_rn(f);
        __nv_bfloat16 l = __float2bfloat16_rn(f - __bfloat162float(h));
        size_t o = (size_t)(n0 + row) * DMODEL + k0 + tx;
        th[o] = h; tl[o] = l;
    }
}

__global__ __launch_bounds__(256) void bcat_kernel(
    const float* __restrict__ bq, const float* __restrict__ bk,
    const float* __restrict__ bv, float* __restrict__ o)
{
    int i = blockIdx.x * 256 + threadIdx.x;
    if (i >= NQKV) return;
    o[i] = (i < DMODEL) ? bq[i] : (i < 2*DMODEL) ? bk[i - DMODEL] : bv[i - 2*DMODEL];
}

// ---------------------------------------------------------------------------
// HMMA GEMM, cp.async 2-stage pipeline.
// C = (Ah+Al)[M,768] @ (Bh+Bl)^T + bias.  A stride 768; out stride = ostride.
// mode 0: fp32 Cf; mode 1: bf16 hi/lo (Oh, Ol).
// Tile 128x64x64; 256 thr = 8 warps (4m x 2n). Stage = 48KB, 2 stages (96KB dyn).
// ---------------------------------------------------------------------------
#define GST 49152
#define G_AH 0
#define G_AL 16384
#define G_BH 32768
#define G_BL 40960
#define NKC  (DMODEL/64)   // 12

__global__ __launch_bounds__(256) void gemm_hmma_kernel(
    const __nv_bfloat16* __restrict__ Ah, const __nv_bfloat16* __restrict__ Al,
    const __nv_bfloat16* __restrict__ Bh, const __nv_bfloat16* __restrict__ Bl,
    const float* __restrict__ bias, float* __restrict__ Cf,
    __nv_bfloat16* __restrict__ Oh, __nv_bfloat16* __restrict__ Ol,
    int mode, int ostride)
{
    extern __shared__ char smem[];
    const uint32_t sb = smem_u32(smem);
    const int tid  = threadIdx.x;
    const int lane = tid & 31, warp = tid >> 5;
    const int wm   = warp & 3, wn = warp >> 2;
    const int m0   = blockIdx.y * 128, n0 = blockIdx.x * 64;
    const int mw   = wm * 32, nw = wn * 32;

    auto prefetch = [&](int kc, int st) {
        const uint32_t base = sb + st * GST;
        #pragma unroll
        for (int r = 0; r < 4; r++) {
            int idx = tid + 256 * r;
            int row = idx >> 3, c16 = idx & 7;
            size_t g = (size_t)(m0 + row) * DMODEL + kc * 64 + c16 * 8;
            uint32_t off = SWZ128((uint32_t)(row * 128 + c16 * 16));
            cp16(base + G_AH + off, Ah + g);
            cp16(base + G_AL + off, Al + g);
        }
        #pragma unroll
        for (int r = 0; r < 2; r++) {
            int idx = tid + 256 * r;
            int row = idx >> 3, c16 = idx & 7;
            size_t g = (size_t)(n0 + row) * DMODEL + kc * 64 + c16 * 8;
            uint32_t off = SWZ128((uint32_t)(row * 128 + c16 * 16));
            cp16(base + G_BH + off, Bh + g);
            cp16(base + G_BL + off, Bl + g);
        }
        cp_commit();
    };

    float acc[2][4][4] = {};

    const int a_row = (lane & 15);
    const int a_col8 = (lane >> 4) * 8;
    const int b_row = ((lane >> 4) << 3) + (lane & 7);
    const int b_col8 = ((lane >> 3) & 1) * 8;

    prefetch(0, 0);

    for (int kc = 0; kc < NKC; kc++) {
        if (kc + 1 < NKC) { prefetch(kc + 1, (kc + 1) & 1); cp_wait<1>(); }
        else              { cp_wait<0>(); }
        __syncthreads();

        const uint32_t base = sb + (kc & 1) * GST;
        #pragma unroll
        for (int ks = 0; ks < 4; ks++) {
            const int ko = ks * 16;
            uint32_t ah[2][4], al[2][4], bh[2][4], bl[2][4];
            #pragma unroll
            for (int mi = 0; mi < 2; mi++) {
                uint32_t off = SWZ128((uint32_t)(
                    (mw + mi * 16 + a_row) * 128 + (ko + a_col8) * 2));
                ldsm_x4(ah[mi], base + G_AH + off);
                ldsm_x4(al[mi], base + G_AL + off);
            }
            #pragma unroll
            for (int hf = 0; hf < 2; hf++) {
                uint32_t off = SWZ128((uint32_t)(
                    (nw + hf * 16 + b_row) * 128 + (ko + b_col8) * 2));
                ldsm_x4(bh[hf], base + G_BH + off);
                ldsm_x4(bl[hf], base + G_BL + off);
            }
            #pragma unroll
            for (int mi = 0; mi < 2; mi++) {
                #pragma unroll
                for (int ni = 0; ni < 4; ni++) {
                    const uint32_t* bhf = &bh[ni >> 1][(ni & 1) * 2];
                    const uint32_t* blf = &bl[ni >> 1][(ni & 1) * 2];
                    mma_bf16(acc[mi][ni], ah[mi], bhf);
                    mma_bf16(acc[mi][ni], ah[mi], blf);
                    mma_bf16(acc[mi][ni], al[mi], bhf);
                }
            }
        }
        __syncthreads();
    }

    const int er = lane >> 2, ec = (lane & 3) * 2;
    #pragma unroll
    for (int mi = 0; mi < 2; mi++) {
        #pragma unroll
        for (int ni = 0; ni < 4; ni++) {
            int row = m0 + mw + mi * 16 + er;
            int col = n0 + nw + ni * 8 + ec;
            float2 b2 = *(const float2*)&bias[col];
            float v0 = acc[mi][ni][0] + b2.x, v1 = acc[mi][ni][1] + b2.y;
            float v2 = acc[mi][ni][2] + b2.x, v3 = acc[mi][ni][3] + b2.y;
            if (mode == 0) {
                *(float2*)&Cf[(size_t)row * ostride + col] = make_float2(v0, v1);
                *(float2*)&Cf[(size_t)(row + 8) * ostride + col] = make_float2(v2, v3);
            } else {
                uint32_t h0, l0, h1, l1;
                split2(v0, v1, h0, l0);
                split2(v2, v3, h1, l1);
                *(uint32_t*)&Oh[(size_t)row * ostride + col] = h0;
                *(uint32_t*)&Ol[(size_t)row * ostride + col] = l0;
                *(uint32_t*)&Oh[(size_t)(row + 8) * ostride + col] = h1;
                *(uint32_t*)&Ol[(size_t)(row + 8) * ostride + col] = l1;
            }
        }
    }
}

// ---------------------------------------------------------------------------
// Tensor-core causal flash attention, cp.async double-buffered K/V.
// CTA: 128 q-rows x one (b,h). 256 thr = 8 warps, 16 q-rows each. Key tiles 64.
// q/k/v packed in qkv buffers: row = tok (s*BATCH+b), stride 2304;
// q cols [0,768), k cols [768,1536), v cols [1536,2304); head offset h*64.
// smem: Q_H 16K | Q_L 16K | 2 stages x (K_H 8K | K_L 8K | V_H 8K | V_L 8K).
// ---------------------------------------------------------------------------
#define AQH 0
#define AQL 16384
#define ASTAGE 32768
#define ASTS 32768

__global__ __launch_bounds__(256) void attn_tc_kernel(
    const __nv_bfloat16* __restrict__ qkvh, const __nv_bfloat16* __restrict__ qkvl,
    __nv_bfloat16* __restrict__ yh, __nv_bfloat16* __restrict__ yl)
{
    extern __shared__ char smem[];
    const uint32_t sb = smem_u32(smem);
    const int tid  = threadIdx.x;
    const int lane = tid & 31, warp = tid >> 5;
    const int bx   = gridDim.x - 1 - blockIdx.x;      // heavy tiles first
    const int bh_  = blockIdx.y;
    const int b    = bh_ / NH, h = bh_ % NH;
    const int q0   = bx * 128;
    const int mw   = warp * 16;

    const int a_row  = lane & 15;
    const int a_col8 = (lane >> 4) * 8;
    const int b_row  = ((lane >> 4) << 3) + (lane & 7);
    const int b_col8 = ((lane >> 3) & 1) * 8;
    const int er = lane >> 2, ec = (lane & 3) * 2;

    auto prefetchKV = [&](int kb, int st) {
        const uint32_t base = sb + ASTAGE + st * ASTS;
        const int k0 = kb * 64;
        #pragma unroll
        for (int r = 0; r < 2; r++) {
            int idx = tid + 256 * r;
            int row = idx >> 3, c16 = idx & 7;
            size_t gk = (size_t)((k0 + row) * BATCH + b) * NQKV + DMODEL + h * HD + c16 * 8;
            size_t gv = gk + DMODEL;
            uint32_t off = SWZ128((uint32_t)(row * 128 + c16 * 16));
            cp16(base + off,         qkvh + gk);
            cp16(base + 8192 + off,  qkvl + gk);
            cp16(base + 16384 + off, qkvh + gv);
            cp16(base + 24576 + off, qkvl + gv);
        }
        cp_commit();
    };

    // --- load Q tile (hi/lo) into smem (plain loads, once) ---
    #pragma unroll
    for (int r = 0; r < 4; r++) {
        int idx = tid + 256 * r;
        int row = idx >> 3, c16 = idx & 7;
        size_t g = (size_t)((q0 + row) * BATCH + b) * NQKV + h * HD + c16 * 8;
        uint32_t off = SWZ128((uint32_t)(row * 128 + c16 * 16));
        *(uint4*)(smem + AQH + off) = *(const uint4*)&qkvh[g];
        *(uint4*)(smem + AQL + off) = *(const uint4*)&qkvl[g];
    }
    prefetchKV(0, 0);
    __syncthreads();

    // --- Q fragments (held all kernel) ---
    uint32_t aqh[4][4], aql[4][4];
    #pragma unroll
    for (int ks = 0; ks < 4; ks++) {
        uint32_t off = SWZ128((uint32_t)((mw + a_row) * 128 + (ks * 16 + a_col8) * 2));
        ldsm_x4(aqh[ks], sb + AQH + off);
        ldsm_x4(aql[ks], sb + AQL + off);
    }

    float o[8][4] = {};
    float m_[2] = {-1e30f, -1e30f};
    float l_[2] = {0.f, 0.f};

    const int ntiles = 2 * bx + 2;
    for (int kb = 0; kb < ntiles; kb++) {
        if (kb + 1 < ntiles) { prefetchKV(kb + 1, (kb + 1) & 1); cp_wait<1>(); }
        else                 { cp_wait<0>(); }
        __syncthreads();

        const int k0 = kb * 64;
        const uint32_t base = sb + ASTAGE + (kb & 1) * ASTS;
        const uint32_t kH = base, kL = base + 8192, vH = base + 16384, vL = base + 24576;

        if (k0 <= q0 + mw + 15) {   // else: tile fully above this warp's diagonal
            // --- S = Q @ K^T (3-MMA split) ---
            float s[8][4] = {};
            #pragma unroll
            for (int ks = 0; ks < 4; ks++) {
                uint32_t kbh[4][4], kbl[4][4];
                #pragma unroll
                for (int nf2 = 0; nf2 < 4; nf2++) {
                    uint32_t off = SWZ128((uint32_t)(
                        (nf2 * 16 + b_row) * 128 + (ks * 16 + b_col8) * 2));
                    ldsm_x4(kbh[nf2], kH + off);
                    ldsm_x4(kbl[nf2], kL + off);
                }
                #pragma unroll
                for (int nf = 0; nf < 8; nf++) {
                    const uint32_t* Bh = &kbh[nf >> 1][(nf & 1) * 2];
                    const uint32_t* Bl = &kbl[nf >> 1][(nf & 1) * 2];
                    mma_bf16(s[nf], aqh[ks], Bh);
                    mma_bf16(s[nf], aqh[ks], Bl);
                    mma_bf16(s[nf], aql[ks], Bh);
                }
            }

            // --- scale + causal mask (only if tile crosses this warp's rows) ---
            if (k0 + 63 > q0 + mw) {
                #pragma unroll
                for (int nf = 0; nf < 8; nf++) {
                    #pragma unroll
                    for (int c = 0; c < 4; c++) {
                        int key = k0 + nf * 8 + ec + (c & 1);
                        int qr  = q0 + mw + er + (c >> 1) * 8;
                        s[nf][c] = (key <= qr) ? s[nf][c] * 0.125f : -1e30f;
                    }
                }
            } else {
                #pragma unroll
                for (int nf = 0; nf < 8; nf++)
                    #pragma unroll
                    for (int c = 0; c < 4; c++) s[nf][c] *= 0.125f;
            }

            // --- online softmax ---
            float mx0 = -1e30f, mx1 = -1e30f;
            #pragma unroll
            for (int nf = 0; nf < 8; nf++) {
                mx0 = fmaxf(mx0, fmaxf(s[nf][0], s[nf][1]));
                mx1 = fmaxf(mx1, fmaxf(s[nf][2], s[nf][3]));
            }
            mx0 = fmaxf(mx0, __shfl_xor_sync(0xffffffffu, mx0, 1));
            mx0 = fmaxf(mx0, __shfl_xor_sync(0xffffffffu, mx0, 2));
            mx1 = fmaxf(mx1, __shfl_xor_sync(0xffffffffu, mx1, 1));
            mx1 = fmaxf(mx1, __shfl_xor_sync(0xffffffffu, mx1, 2));
            float mn0 = fmaxf(m_[0], mx0), mn1 = fmaxf(m_[1], mx1);
            float al0 = __expf(m_[0] - mn0), al1 = __expf(m_[1] - mn1);
            m_[0] = mn0; m_[1] = mn1;
            float sum0 = 0.f, sum1 = 0.f;
            #pragma unroll
            for (int nf = 0; nf < 8; nf++) {
                s[nf][0] = __expf(s[nf][0] - mn0); sum0 += s[nf][0];
                s[nf][1] = __expf(s[nf][1] - mn0); sum0 += s[nf][1];
                s[nf][2] = __expf(s[nf][2] - mn1); sum1 += s[nf][2];
                s[nf][3] = __expf(s[nf][3] - mn1); sum1 += s[nf][3];
            }
            sum0 += __shfl_xor_sync(0xffffffffu, sum0, 1);
            sum0 += __shfl_xor_sync(0xffffffffu, sum0, 2);
            sum1 += __shfl_xor_sync(0xffffffffu, sum1, 1);
            sum1 += __shfl_xor_sync(0xffffffffu, sum1, 2);
            l_[0] = l_[0] * al0 + sum0;
            l_[1] = l_[1] * al1 + sum1;
            #pragma unroll
            for (int df = 0; df < 8; df++) {
                o[df][0] *= al0; o[df][1] *= al0;
                o[df][2] *= al1; o[df][3] *= al1;
            }

            // --- O += P @ V (P split hi/lo; V^T via movmatrix) ---
            #pragma unroll
            for (int ks = 0; ks < 4; ks++) {
                uint32_t aph[4], apl[4];
                split2(s[2*ks][0],   s[2*ks][1],   aph[0], apl[0]);
                split2(s[2*ks][2],   s[2*ks][3],   aph[1], apl[1]);
                split2(s[2*ks+1][0], s[2*ks+1][1], aph[2], apl[2]);
                split2(s[2*ks+1][2], s[2*ks+1][3], aph[3], apl[3]);
                #pragma unroll
                for (int df2 = 0; df2 < 4; df2++) {
                    uint32_t off = SWZ128((uint32_t)(
                        (ks * 16 + a_row) * 128 + (df2 * 16 + a_col8) * 2));
                    uint32_t rvh[4], rvl[4];
                    ldsm_x4(rvh, vH + off);
                    ldsm_x4(rvl, vL + off);
                    uint32_t tvh[4], tvl[4];
                    #pragma unroll
                    for (int i = 0; i < 4; i++) { tvh[i] = movm_t(rvh[i]); tvl[i] = movm_t(rvl[i]); }
                    mma_bf16(o[2*df2],   aph, &tvh[0]);
                    mma_bf16(o[2*df2],   aph, &tvl[0]);
                    mma_bf16(o[2*df2],   apl, &tvh[0]);
                    mma_bf16(o[2*df2+1], aph, &tvh[2]);
                    mma_bf16(o[2*df2+1], aph, &tvl[2]);
                    mma_bf16(o[2*df2+1], apl, &tvh[2]);
                }
            }
        }
        __syncthreads();
    }

    // --- epilogue: normalize, split, store bf16 hi/lo ---
    float inv0 = 1.f / l_[0], inv1 = 1.f / l_[1];
    int tok0 = (q0 + mw + er) * BATCH + b;
    int tok1 = tok0 + 8 * BATCH;
    #pragma unroll
    for (int df = 0; df < 8; df++) {
        int col = h * HD + df * 8 + ec;
        uint32_t h0, l0, h1, l1;
        split2(o[df][0] * inv0, o[df][1] * inv0, h0, l0);
        split2(o[df][2] * inv1, o[df][3] * inv1, h1, l1);
        *(uint32_t*)&yh[(size_t)tok0 * DMODEL + col] = h0;
        *(uint32_t*)&yl[(size_t)tok0 * DMODEL + col] = l0;
        *(uint32_t*)&yh[(size_t)tok1 * DMODEL + col] = h1;
        *(uint32_t*)&yl[(size_t)tok1 * DMODEL + col] = l1;
    }
}

// ---------------------------------------------------------------------------
extern "C" void kernel_launch(void* const* d_in, const int* in_sizes, int n_in,
                              void* d_out, int out_size)
{
    const float* x  = (const float*)d_in[0];
    const float* Wq = (const float*)d_in[1];
    const float* bq = (const float*)d_in[2];
    const float* Wk = (const float*)d_in[3];
    const float* bk = (const float*)d_in[4];
    const float* Wv = (const float*)d_in[5];
    const float* bv = (const float*)d_in[6];
    const float* Wo = (const float*)d_in[7];
    const float* bo = (const float*)d_in[8];
    float* out = (float*)d_out;

    __nv_bfloat16 *xs_hi, *xs_lo, *qkvh, *qkvl, *ys_hi, *ys_lo, *wt_hi, *wt_lo;
    float* bqkv;
    cudaGetSymbolAddress((void**)&xs_hi, g_xs_hi);
    cudaGetSymbolAddress((void**)&xs_lo, g_xs_lo);
    cudaGetSymbolAddress((void**)&qkvh, g_qkvh);
    cudaGetSymbolAddress((void**)&qkvl, g_qkvl);
    cudaGetSymbolAddress((void**)&ys_hi, g_ys_hi);
    cudaGetSymbolAddress((void**)&ys_lo, g_ys_lo);
    cudaGetSymbolAddress((void**)&wt_hi, g_wt_hi);
    cudaGetSymbolAddress((void**)&wt_lo, g_wt_lo);
    cudaGetSymbolAddress((void**)&bqkv, g_bqkv);

    static bool attr_set = false;
    if (!attr_set) {
        cudaFuncSetAttribute(gemm_hmma_kernel,
                             cudaFuncAttributeMaxDynamicSharedMemorySize, 2*GST);
        cudaFuncSetAttribute(attn_tc_kernel,
                             cudaFuncAttributeMaxDynamicSharedMemorySize, ASTAGE + 2*ASTS);
        attr_set = true;
    }

    const size_t WSZ = (size_t)DMODEL * DMODEL;

    dim3 wtGrid(DMODEL/32, DMODEL/32), wtBlk(32, 8);
    wtsplit_kernel<<<wtGrid, wtBlk>>>(Wq, wt_hi + 0*WSZ, wt_lo + 0*WSZ);
    wtsplit_kernel<<<wtGrid, wtBlk>>>(Wk, wt_hi + 1*WSZ, wt_lo + 1*WSZ);
    wtsplit_kernel<<<wtGrid, wtBlk>>>(Wv, wt_hi + 2*WSZ, wt_lo + 2*WSZ);
    wtsplit_kernel<<<wtGrid, wtBlk>>>(Wo, wt_hi + 3*WSZ, wt_lo + 3*WSZ);
    bcat_kernel<<<(NQKV + 255)/256, 256>>>(bq, bk, bv, bqkv);

    int n4 = NTOK * DMODEL / 4;
    fsplit_kernel<<<n4 / 256, 256>>>(x, xs_hi, xs_lo, n4);

    // Fused QKV projection: N = 2304 (q,k,v weight slabs are contiguous)
    dim3 qkvGrid(NQKV/64, NTOK/128);   // (36, 32)
    gemm_hmma_kernel<<<qkvGrid, 256, 2*GST>>>(
        xs_hi, xs_lo, wt_hi, wt_lo, bqkv, nullptr, qkvh, qkvl, 1, NQKV);

    dim3 aGrid(SEQ/128, BATCH*NH);     // (16, 24)
    attn_tc_kernel<<<aGrid, 256, ASTAGE + 2*ASTS>>>(qkvh, qkvl, ys_hi, ys_lo);

    dim3 oGrid(DMODEL/64, NTOK/128);   // (12, 32)
    gemm_hmma_kernel<<<oGrid, 256, 2*GST>>>(
        ys_hi, ys_lo, wt_hi + 3*WSZ, wt_lo + 3*WSZ, bo, out, nullptr, nullptr, 0, DMODEL);
}